// round 6
// baseline (speedup 1.0000x reference)
#include <cuda_runtime.h>
#include <cuda_bf16.h>

#define Nn 22
#define Fd 192
#define NB4 4
#define MR 96
#define THREADS 256
#define NBATCH_MAX 16384
#define TROWS (NBATCH_MAX*Nn)

typedef unsigned int u32;
typedef unsigned short u16;

// ---- SMEM layout (bytes) ----
#define OFF_ADJ 0            // 484 f
#define OFF_AVS 1952         // 768 f
#define OFF_WS  5024         // 4 x 550 f
#define OFF_A   13824
#define ASTR    400          // 96 rows x 192 bf16 (16B-aligned, conflict-free for LDSM)
#define OFF_AHI OFF_A
#define OFF_ALO (OFF_A + 38400)
#define OFF_B   90624        // dbuf: per buf hi plane 15360 + lo plane 15360
#define BSTR    80           // 192 rows x 32 bf16
#define BPL     15360
#define BBUF    30720
#define OFF_WHS 152064       // 96 x 193 fp32
#define WS_S    193
#define SMEM_TOTAL 226176

// ---- device-global scratch (sanctioned path) ----
static __device__ u32 g_hcp[(long long)TROWS*384];     // packed (hi<<16)|lo per element
static __device__ __nv_bfloat16 g_w12t_hi[384*192];
static __device__ __nv_bfloat16 g_w12t_lo[384*192];
static __device__ __nv_bfloat16 g_wot_hi[192*384];
static __device__ __nv_bfloat16 g_wot_lo[192*384];

// ---- helpers ----
__device__ __forceinline__ u32 smem_u32(const void* p){
    u32 a;
    asm("{ .reg .u64 t; cvta.to.shared.u64 t, %1; cvt.u32.u64 %0, t; }" : "=r"(a) : "l"(p));
    return a;
}
__device__ __forceinline__ void split_bf16(float v, u16& h, u16& l){
    __nv_bfloat16 hb = __float2bfloat16(v);
    float hf = __bfloat162float(hb);
    __nv_bfloat16 lb = __float2bfloat16(v - hf);
    h = __bfloat16_as_ushort(hb);
    l = __bfloat16_as_ushort(lb);
}
__device__ __forceinline__ float elu1(float v){ return (v > 0.0f) ? v : (__expf(v) - 1.0f); }

#define CPA16(sa, g) asm volatile("cp.async.cg.shared.global [%0], [%1], 16;" :: "r"((u32)(sa)), "l"(g) : "memory")
#define CPC()  asm volatile("cp.async.commit_group;" ::: "memory")
#define CPW1() asm volatile("cp.async.wait_group 1;" ::: "memory")
#define CPW0() asm volatile("cp.async.wait_group 0;" ::: "memory")

__device__ __forceinline__ void mma_bf16(float* c, const u32* a, u32 b0, u32 b1){
    asm volatile("mma.sync.aligned.m16n8k16.row.col.f32.bf16.bf16.f32 "
        "{%0,%1,%2,%3}, {%4,%5,%6,%7}, {%8,%9}, {%0,%1,%2,%3};"
        : "+f"(c[0]),"+f"(c[1]),"+f"(c[2]),"+f"(c[3])
        : "r"(a[0]),"r"(a[1]),"r"(a[2]),"r"(a[3]),"r"(b0),"r"(b1));
}
__device__ __forceinline__ void ldsm4(u32 a, u32* r){
    asm volatile("ldmatrix.sync.aligned.m8n8.x4.shared.b16 {%0,%1,%2,%3}, [%4];"
        : "=r"(r[0]),"=r"(r[1]),"=r"(r[2]),"=r"(r[3]) : "r"(a));
}

__device__ __forceinline__ void warp_softmax(const float* __restrict__ ev, const float* __restrict__ adjs,
                                             float* __restrict__ attw, int lane)
{
    if (lane < Nn) {
        int i = lane;
        float esrc = ev[i];
        float vals[Nn];
        float mx = -1e30f;
#pragma unroll
        for (int j = 0; j < Nn; j++) {
            if (adjs[i * Nn + j] != 0.0f) {
                float v = esrc + ev[Nn + j];
                v = (v > 0.0f) ? v : 0.2f * v;
                vals[j] = v;
                mx = fmaxf(mx, v);
            } else vals[j] = -1e30f;
        }
        float ssum = 0.0f;
#pragma unroll
        for (int j = 0; j < Nn; j++) {
            float e = (vals[j] > -1e29f) ? __expf(vals[j] - mx) : 0.0f;
            vals[j] = e; ssum += e;
        }
        float inv = 1.0f / ssum;
#pragma unroll
        for (int j = 0; j < Nn; j++) attw[i * 23 + j] = vals[j] * inv;
    }
}

// stream one B chunk: 192 n-rows x 32 k (hi+lo) via cp.async 16B
__device__ __forceinline__ void issue_b(u32 dst, const __nv_bfloat16* gh, const __nv_bfloat16* gl,
                                        int tid, int rs)
{
#pragma unroll
    for (int q = 0; q < 6; q++) {
        int lin = tid + THREADS * q;        // 0..1535
        int plane = lin / 768;
        int rem = lin - plane * 768;
        int row = rem >> 2, piece = rem & 3;
        const __nv_bfloat16* src = (plane ? gl : gh) + row * rs + piece * 8;
        CPA16(dst + plane * BPL + row * BSTR + piece * 16, src);
    }
}

// GEMM mainloop over 6 k-chunks against resident A (ldmatrix path)
__device__ __forceinline__ void gemm6(u32 sb, float acc[3][6][4],
                                      const __nv_bfloat16* bh0, const __nv_bfloat16* bl0, int rs,
                                      int tid, int wm, int wn, int lane)
{
    const u32 laneA = (u32)((lane & 15) * ASTR + (lane >> 4) * 16);
    const u32 laneB = (u32)((lane & 15) * BSTR + (lane >> 4) * 16);
    const u32 Abase = sb + OFF_AHI + wm * 48 * ASTR + laneA;

    issue_b(sb + OFF_B, bh0, bl0, tid, rs);
    CPC();
    for (int kc = 0; kc < 6; kc++) {
        int buf = kc & 1;
        __syncthreads();
        if (kc < 5) {
            issue_b(sb + OFF_B + (buf ^ 1) * BBUF, bh0 + (kc + 1) * 32, bl0 + (kc + 1) * 32, tid, rs);
            CPC(); CPW1();
        } else CPW0();
        __syncthreads();

        const u32 Ah = Abase + kc * 64;
        const u32 Bh = sb + OFF_B + buf * BBUF + wn * 48 * BSTR + laneB;
#pragma unroll
        for (int s = 0; s < 2; s++) {
            u32 ah[3][4], al[3][4], bh[3][4], bl[3][4];
#pragma unroll
            for (int mt = 0; mt < 3; mt++) {
                ldsm4(Ah + mt * 16 * ASTR + s * 32, ah[mt]);
                ldsm4(Ah + 38400 + mt * 16 * ASTR + s * 32, al[mt]);
            }
#pragma unroll
            for (int t = 0; t < 3; t++) {
                ldsm4(Bh + t * 16 * BSTR + s * 32, bh[t]);
                ldsm4(Bh + BPL + t * 16 * BSTR + s * 32, bl[t]);
            }
#pragma unroll
            for (int mt = 0; mt < 3; mt++)
#pragma unroll
                for (int t = 0; t < 3; t++) {
                    mma_bf16(acc[mt][2*t],   ah[mt], bh[t][0], bh[t][2]);
                    mma_bf16(acc[mt][2*t+1], ah[mt], bh[t][1], bh[t][3]);
                    mma_bf16(acc[mt][2*t],   ah[mt], bl[t][0], bl[t][2]);
                    mma_bf16(acc[mt][2*t+1], ah[mt], bl[t][1], bl[t][3]);
                    mma_bf16(acc[mt][2*t],   al[mt], bh[t][0], bh[t][2]);
                    mma_bf16(acc[mt][2*t+1], al[mt], bh[t][1], bh[t][3]);
                }
        }
    }
}

// ================= prep =================
__global__ void k_prep(const float* __restrict__ W1, const float* __restrict__ W2,
                       const float* __restrict__ Wo)
{
    int idx = blockIdx.x * blockDim.x + threadIdx.x;
    if (idx < 384 * 192) {
        int n = idx / 192, k = idx % 192;
        float v = (n < 192) ? W1[k * 192 + n] : W2[k * 192 + (n - 192)];
        u16 h, l; split_bf16(v, h, l);
        g_w12t_hi[idx] = __ushort_as_bfloat16(h);
        g_w12t_lo[idx] = __ushort_as_bfloat16(l);
    } else if (idx < 2 * 384 * 192) {
        int j = idx - 384 * 192;
        int n = j / 384, k = j % 384;
        float v = Wo[k * 192 + n];
        u16 h, l; split_bf16(v, h, l);
        g_wot_hi[j] = __ushort_as_bfloat16(h);
        g_wot_lo[j] = __ushort_as_bfloat16(l);
    }
}

// ================= K1: GEMM1 (per head) + head attention -> g_hcp =================
__global__ __launch_bounds__(THREADS, 1)
void k1(const float* __restrict__ x, const float* __restrict__ adj,
        const float* __restrict__ a1, const float* __restrict__ a2, int nbatch)
{
    extern __shared__ char smc[];
    float* smf = (float*)smc;
    const u32 sb = smem_u32(smc);
    const int tid = threadIdx.x, wid = tid >> 5, lane = tid & 31;
    const int l4 = lane >> 2, lq = lane & 3;
    const int wm = wid & 1, wn = wid >> 1;
    const int wb = wid >> 1, sd = wid & 1;     // attention roles
    const int b0 = blockIdx.x * NB4;
    const int nb = min(NB4, nbatch - b0);
    const int nrows = nb * Nn;
    const long long row0 = (long long)b0 * Nn;

    float* adjs = smf + OFF_ADJ / 4;
    float* avs  = smf + OFF_AVS / 4;
    float* whs  = (float*)(smc + OFF_WHS);

    for (int i = tid; i < Nn * Nn; i += THREADS) adjs[i] = adj[i];
    for (int i = tid; i < 768; i += THREADS) avs[i] = (i < 384) ? a1[i] : a2[i - 384];

    // A = split(x): 96 rows x 192
    for (int idx = tid; idx < MR * 96; idx += THREADS) {
        int r = idx / 96, kp = idx % 96;
        float2 v = make_float2(0.f, 0.f);
        if (r < nrows) v = *(const float2*)(x + (row0 + r) * Fd + kp * 2);
        u16 h0,l0,h1,l1;
        split_bf16(v.x, h0, l0); split_bf16(v.y, h1, l1);
        *(u32*)(smc + OFF_AHI + r * ASTR + kp * 4) = h0 | ((u32)h1 << 16);
        *(u32*)(smc + OFF_ALO + r * ASTR + kp * 4) = l0 | ((u32)l1 << 16);
    }

    for (int h = 0; h < 2; h++) {
        float acc[3][6][4];
#pragma unroll
        for (int mt = 0; mt < 3; mt++)
#pragma unroll
            for (int nt = 0; nt < 6; nt++)
#pragma unroll
                for (int q = 0; q < 4; q++) acc[mt][nt][q] = 0.0f;

        gemm6(sb, acc, g_w12t_hi + h * 192 * 192, g_w12t_lo + h * 192 * 192, 192,
              tid, wm, wn, lane);

        __syncthreads();
#pragma unroll
        for (int mt = 0; mt < 3; mt++)
#pragma unroll
            for (int nt = 0; nt < 6; nt++) {
                int r = wm * 48 + mt * 16 + l4, c = wn * 48 + nt * 8 + lq * 2;
                whs[r * WS_S + c]           = acc[mt][nt][0];
                whs[r * WS_S + c + 1]       = acc[mt][nt][1];
                whs[(r + 8) * WS_S + c]     = acc[mt][nt][2];
                whs[(r + 8) * WS_S + c + 1] = acc[mt][nt][3];
            }
        __syncthreads();

        // attention head h: warp (wb, sd)
        float* ev   = smf + OFF_WS / 4 + wb * 550;
        float* attw = ev + 44;
        if (wb < nb) {
            const float* av = avs + h * 384 + sd * 192;
            for (int i = 0; i < Nn; i++) {
                const float* rw = whs + (wb * Nn + i) * WS_S;
                float s = 0.0f;
#pragma unroll
                for (int j = 0; j < 6; j++) s += rw[lane + 32 * j] * av[lane + 32 * j];
#pragma unroll
                for (int o = 16; o; o >>= 1) s += __shfl_xor_sync(0xffffffffu, s, o);
                if (lane == 0) ev[sd * Nn + i] = s;
            }
        }
        __syncthreads();
        if (wb < nb && sd == 0) warp_softmax(ev, adjs, attw, lane);
        __syncthreads();
        if (wb < nb) {
#pragma unroll
            for (int p = 0; p < 3; p++) {
                int c = sd * 96 + p * 32 + lane;
                float wv[Nn];
#pragma unroll
                for (int j = 0; j < Nn; j++) wv[j] = whs[(wb * Nn + j) * WS_S + c];
#pragma unroll 2
                for (int i = 0; i < Nn; i++) {
                    const float* aw = attw + i * 23;
                    float s = 0.0f;
#pragma unroll
                    for (int j = 0; j < Nn; j++) s += aw[j] * wv[j];
                    s = elu1(s);
                    u16 hh, ll; split_bf16(s, hh, ll);
                    // packed coalesced store: lanes contiguous over c
                    g_hcp[(row0 + wb * Nn + i) * 384 + h * 192 + c] = ((u32)hh << 16) | ll;
                }
            }
        }
        __syncthreads();
    }
}

// ================= K2: GEMM2 (K=384) + output attention + residual =================
__global__ __launch_bounds__(THREADS, 1)
void k2(const float* __restrict__ x, const float* __restrict__ adj,
        const float* __restrict__ ao, float* __restrict__ out, int nbatch)
{
    extern __shared__ char smc[];
    float* smf = (float*)smc;
    const u32 sb = smem_u32(smc);
    const int tid = threadIdx.x, wid = tid >> 5, lane = tid & 31;
    const int l4 = lane >> 2, lq = lane & 3;
    const int wm = wid & 1, wn = wid >> 1;
    const int wb = wid >> 1, sd = wid & 1;
    const int b0 = blockIdx.x * NB4;
    const int nb = min(NB4, nbatch - b0);
    const int nrows = nb * Nn;
    const long long row0 = (long long)b0 * Nn;

    float* adjs = smf + OFF_ADJ / 4;
    float* avs  = smf + OFF_AVS / 4;
    float* who  = (float*)(smc + OFF_WHS);

    for (int i = tid; i < Nn * Nn; i += THREADS) adjs[i] = adj[i];
    for (int i = tid; i < 384; i += THREADS) avs[i] = ao[i];

    float acc[3][6][4];
#pragma unroll
    for (int mt = 0; mt < 3; mt++)
#pragma unroll
        for (int nt = 0; nt < 6; nt++)
#pragma unroll
            for (int q = 0; q < 4; q++) acc[mt][nt][q] = 0.0f;

    for (int kh = 0; kh < 2; kh++) {
        __syncthreads();   // prior A reads complete before overwrite
        // load packed A half from g_hcp, unpack to hi/lo planes
        for (int idx = tid; idx < MR * 48; idx += THREADS) {
            int r = idx / 48, q4 = (idx % 48) * 4;     // 4 elements per uint4
            uint4 v = make_uint4(0, 0, 0, 0);
            if (r < nrows)
                v = *(const uint4*)(g_hcp + (row0 + r) * 384 + kh * 192 + q4);
            u32 hi0 = __byte_perm(v.x, v.y, 0x7632);
            u32 lo0 = __byte_perm(v.x, v.y, 0x5410);
            u32 hi1 = __byte_perm(v.z, v.w, 0x7632);
            u32 lo1 = __byte_perm(v.z, v.w, 0x5410);
            *(uint2*)(smc + OFF_AHI + r * ASTR + q4 * 2) = make_uint2(hi0, hi1);
            *(uint2*)(smc + OFF_ALO + r * ASTR + q4 * 2) = make_uint2(lo0, lo1);
        }
        gemm6(sb, acc, g_wot_hi + kh * 192, g_wot_lo + kh * 192, 384,
              tid, wm, wn, lane);
    }

    __syncthreads();
#pragma unroll
    for (int mt = 0; mt < 3; mt++)
#pragma unroll
        for (int nt = 0; nt < 6; nt++) {
            int r = wm * 48 + mt * 16 + l4, c = wn * 48 + nt * 8 + lq * 2;
            who[r * WS_S + c]           = acc[mt][nt][0];
            who[r * WS_S + c + 1]       = acc[mt][nt][1];
            who[(r + 8) * WS_S + c]     = acc[mt][nt][2];
            who[(r + 8) * WS_S + c + 1] = acc[mt][nt][3];
        }
    __syncthreads();

    float* ev   = smf + OFF_WS / 4 + wb * 550;
    float* attw = ev + 44;
    if (wb < nb) {
        const float* av = avs + sd * 192;
        for (int i = 0; i < Nn; i++) {
            const float* rw = who + (wb * Nn + i) * WS_S;
            float s = 0.0f;
#pragma unroll
            for (int j = 0; j < 6; j++) s += rw[lane + 32 * j] * av[lane + 32 * j];
#pragma unroll
            for (int o = 16; o; o >>= 1) s += __shfl_xor_sync(0xffffffffu, s, o);
            if (lane == 0) ev[sd * Nn + i] = s;
        }
    }
    __syncthreads();
    if (wb < nb && sd == 0) warp_softmax(ev, adjs, attw, lane);
    __syncthreads();
    if (wb < nb) {
#pragma unroll
        for (int p = 0; p < 3; p++) {
            int c = sd * 96 + p * 32 + lane;
            float wv[Nn];
#pragma unroll
            for (int j = 0; j < Nn; j++) wv[j] = who[(wb * Nn + j) * WS_S + c];
#pragma unroll 2
            for (int i = 0; i < Nn; i++) {
                const float* aw = attw + i * 23;
                float s = 0.0f;
#pragma unroll
                for (int j = 0; j < Nn; j++) s += aw[j] * wv[j];
                long long gi = (row0 + wb * Nn + i) * Fd + c;
                out[gi] = elu1(s) + x[gi];
            }
        }
    }
}

extern "C" void kernel_launch(void* const* d_in, const int* in_sizes, int n_in,
                              void* d_out, int out_size)
{
    const float* x   = (const float*)d_in[0];
    const float* adj = (const float*)d_in[1];
    const float* W1  = (const float*)d_in[2];
    const float* a1  = (const float*)d_in[3];
    const float* W2  = (const float*)d_in[4];
    const float* a2  = (const float*)d_in[5];
    const float* Wo  = (const float*)d_in[6];
    const float* ao  = (const float*)d_in[7];
    float* out = (float*)d_out;

    int nbatch = in_sizes[0] / (Nn * Fd);
    int ctas = (nbatch + NB4 - 1) / NB4;

    cudaFuncSetAttribute(k1, cudaFuncAttributeMaxDynamicSharedMemorySize, SMEM_TOTAL);
    cudaFuncSetAttribute(k2, cudaFuncAttributeMaxDynamicSharedMemorySize, SMEM_TOTAL);

    k_prep<<<(2 * 384 * 192 + 255) / 256, 256>>>(W1, W2, Wo);
    k1<<<ctas, THREADS, SMEM_TOTAL>>>(x, adj, a1, a2, nbatch);
    k2<<<ctas, THREADS, SMEM_TOTAL>>>(x, adj, ao, out, nbatch);
}

// round 7
// speedup vs baseline: 1.2210x; 1.2210x over previous
#include <cuda_runtime.h>
#include <cuda_bf16.h>

#define Nn 22
#define Fd 192
#define NB4 4
#define MR 96
#define THREADS 512
#define NBATCH_MAX 16384
#define TROWS (NBATCH_MAX*Nn)

typedef unsigned int u32;
typedef unsigned short u16;

// ---- SMEM layout (bytes) ----
#define OFF_ADJ 0            // 484 f
#define OFF_AVS 1952         // 768 f
#define OFF_WS  5024         // 4 x 550 f
#define OFF_A   13824
#define ASTR    400          // 96 rows x 192 bf16 (16B-aligned, conflict-free for LDSM)
#define OFF_AHI OFF_A
#define OFF_ALO (OFF_A + 38400)
#define OFF_B   90624        // dbuf: per buf hi plane 15360 + lo plane 15360
#define BSTR    80           // 192 rows x 32 bf16
#define BPL     15360
#define BBUF    30720
#define OFF_WHS 152064       // 96 x 193 fp32
#define WS_S    193
#define SMEM_TOTAL 226176

// ---- device-global scratch (sanctioned path) ----
static __device__ u32 g_hcp[(long long)TROWS*384];     // packed (hi<<16)|lo per element
static __device__ __nv_bfloat16 g_w12t_hi[384*192];
static __device__ __nv_bfloat16 g_w12t_lo[384*192];
static __device__ __nv_bfloat16 g_wot_hi[192*384];
static __device__ __nv_bfloat16 g_wot_lo[192*384];

// ---- helpers ----
__device__ __forceinline__ u32 smem_u32(const void* p){
    u32 a;
    asm("{ .reg .u64 t; cvta.to.shared.u64 t, %1; cvt.u32.u64 %0, t; }" : "=r"(a) : "l"(p));
    return a;
}
__device__ __forceinline__ void split_bf16(float v, u16& h, u16& l){
    __nv_bfloat16 hb = __float2bfloat16(v);
    float hf = __bfloat162float(hb);
    __nv_bfloat16 lb = __float2bfloat16(v - hf);
    h = __bfloat16_as_ushort(hb);
    l = __bfloat16_as_ushort(lb);
}
__device__ __forceinline__ float elu1(float v){ return (v > 0.0f) ? v : (__expf(v) - 1.0f); }

#define CPA16(sa, g) asm volatile("cp.async.cg.shared.global [%0], [%1], 16;" :: "r"((u32)(sa)), "l"(g) : "memory")
#define CPC()  asm volatile("cp.async.commit_group;" ::: "memory")
#define CPW1() asm volatile("cp.async.wait_group 1;" ::: "memory")
#define CPW0() asm volatile("cp.async.wait_group 0;" ::: "memory")

__device__ __forceinline__ void mma_bf16(float* c, const u32* a, u32 b0, u32 b1){
    asm volatile("mma.sync.aligned.m16n8k16.row.col.f32.bf16.bf16.f32 "
        "{%0,%1,%2,%3}, {%4,%5,%6,%7}, {%8,%9}, {%0,%1,%2,%3};"
        : "+f"(c[0]),"+f"(c[1]),"+f"(c[2]),"+f"(c[3])
        : "r"(a[0]),"r"(a[1]),"r"(a[2]),"r"(a[3]),"r"(b0),"r"(b1));
}
__device__ __forceinline__ void ldsm4(u32 a, u32* r){
    asm volatile("ldmatrix.sync.aligned.m8n8.x4.shared.b16 {%0,%1,%2,%3}, [%4];"
        : "=r"(r[0]),"=r"(r[1]),"=r"(r[2]),"=r"(r[3]) : "r"(a));
}
__device__ __forceinline__ void ldsm2(u32 a, u32* r){
    asm volatile("ldmatrix.sync.aligned.m8n8.x2.shared.b16 {%0,%1}, [%2];"
        : "=r"(r[0]),"=r"(r[1]) : "r"(a));
}

__device__ __forceinline__ void warp_softmax(const float* __restrict__ ev, const float* __restrict__ adjs,
                                             float* __restrict__ attw, int lane)
{
    if (lane < Nn) {
        int i = lane;
        float esrc = ev[i];
        float vals[Nn];
        float mx = -1e30f;
#pragma unroll
        for (int j = 0; j < Nn; j++) {
            if (adjs[i * Nn + j] != 0.0f) {
                float v = esrc + ev[Nn + j];
                v = (v > 0.0f) ? v : 0.2f * v;
                vals[j] = v;
                mx = fmaxf(mx, v);
            } else vals[j] = -1e30f;
        }
        float ssum = 0.0f;
#pragma unroll
        for (int j = 0; j < Nn; j++) {
            float e = (vals[j] > -1e29f) ? __expf(vals[j] - mx) : 0.0f;
            vals[j] = e; ssum += e;
        }
        float inv = 1.0f / ssum;
#pragma unroll
        for (int j = 0; j < Nn; j++) attw[i * 23 + j] = vals[j] * inv;
    }
}

// stream one B chunk: 192 n-rows x 32 k (hi+lo) via cp.async 16B
__device__ __forceinline__ void issue_b(u32 dst, const __nv_bfloat16* gh, const __nv_bfloat16* gl,
                                        int tid, int rs)
{
#pragma unroll
    for (int q = 0; q < 3; q++) {
        int lin = tid + THREADS * q;        // 0..1535
        int plane = lin / 768;
        int rem = lin - plane * 768;
        int row = rem >> 2, piece = rem & 3;
        const __nv_bfloat16* src = (plane ? gl : gh) + row * rs + piece * 8;
        CPA16(dst + plane * BPL + row * BSTR + piece * 16, src);
    }
}

// GEMM mainloop over 6 k-chunks against resident A; warp tile 48x24; acc[3][3][4]
__device__ __forceinline__ void gemm6(u32 sb, float acc[3][3][4],
                                      const __nv_bfloat16* bh0, const __nv_bfloat16* bl0, int rs,
                                      int tid, int wm, int wn, int lane)
{
    const u32 laneA = (u32)((lane & 15) * ASTR + (lane >> 4) * 16);
    const u32 laneB = (u32)((lane & 7) * BSTR + ((lane >> 3) & 1) * 16);
    const u32 Abase = sb + OFF_AHI + wm * 48 * ASTR + laneA;
    const u32 Bbase = sb + OFF_B + wn * 24 * BSTR + laneB;

    issue_b(sb + OFF_B, bh0, bl0, tid, rs);
    CPC();
    for (int kc = 0; kc < 6; kc++) {
        int buf = kc & 1;
        __syncthreads();
        if (kc < 5) {
            issue_b(sb + OFF_B + (buf ^ 1) * BBUF, bh0 + (kc + 1) * 32, bl0 + (kc + 1) * 32, tid, rs);
            CPC(); CPW1();
        } else CPW0();
        __syncthreads();

        const u32 Ah = Abase + kc * 64;
        const u32 Bh = Bbase + buf * BBUF;
#pragma unroll
        for (int s = 0; s < 2; s++) {
            u32 ah[3][4], al[3][4], bh[3][2], bl[3][2];
#pragma unroll
            for (int mt = 0; mt < 3; mt++) {
                ldsm4(Ah + mt * 16 * ASTR + s * 32, ah[mt]);
                ldsm4(Ah + 38400 + mt * 16 * ASTR + s * 32, al[mt]);
            }
#pragma unroll
            for (int t = 0; t < 3; t++) {
                ldsm2(Bh + t * 8 * BSTR + s * 32, bh[t]);
                ldsm2(Bh + BPL + t * 8 * BSTR + s * 32, bl[t]);
            }
#pragma unroll
            for (int mt = 0; mt < 3; mt++)
#pragma unroll
                for (int t = 0; t < 3; t++) {
                    mma_bf16(acc[mt][t], ah[mt], bh[t][0], bh[t][1]);
                    mma_bf16(acc[mt][t], ah[mt], bl[t][0], bl[t][1]);
                    mma_bf16(acc[mt][t], al[mt], bh[t][0], bh[t][1]);
                }
        }
    }
}

// ================= prep =================
__global__ void k_prep(const float* __restrict__ W1, const float* __restrict__ W2,
                       const float* __restrict__ Wo)
{
    int idx = blockIdx.x * blockDim.x + threadIdx.x;
    if (idx < 384 * 192) {
        int n = idx / 192, k = idx % 192;
        float v = (n < 192) ? W1[k * 192 + n] : W2[k * 192 + (n - 192)];
        u16 h, l; split_bf16(v, h, l);
        g_w12t_hi[idx] = __ushort_as_bfloat16(h);
        g_w12t_lo[idx] = __ushort_as_bfloat16(l);
    } else if (idx < 2 * 384 * 192) {
        int j = idx - 384 * 192;
        int n = j / 384, k = j % 384;
        float v = Wo[k * 192 + n];
        u16 h, l; split_bf16(v, h, l);
        g_wot_hi[j] = __ushort_as_bfloat16(h);
        g_wot_lo[j] = __ushort_as_bfloat16(l);
    }
}

// ================= K1: GEMM1 (per head) + head attention -> g_hcp =================
__global__ __launch_bounds__(THREADS, 1)
void k1(const float* __restrict__ x, const float* __restrict__ adj,
        const float* __restrict__ a1, const float* __restrict__ a2, int nbatch)
{
    extern __shared__ char smc[];
    float* smf = (float*)smc;
    const u32 sb = smem_u32(smc);
    const int tid = threadIdx.x, wid = tid >> 5, lane = tid & 31;
    const int l4 = lane >> 2, lq = lane & 3;
    const int wm = wid & 1, wn = wid >> 1;       // GEMM roles: 2M x 8N
    const int wb = wid >> 2, q = wid & 3;        // attention roles: 4 batches x 4 slices
    const int b0 = blockIdx.x * NB4;
    const int nb = min(NB4, nbatch - b0);
    const int nrows = nb * Nn;
    const long long row0 = (long long)b0 * Nn;

    float* adjs = smf + OFF_ADJ / 4;
    float* avs  = smf + OFF_AVS / 4;
    float* whs  = (float*)(smc + OFF_WHS);

    for (int i = tid; i < Nn * Nn; i += THREADS) adjs[i] = adj[i];
    for (int i = tid; i < 768; i += THREADS) avs[i] = (i < 384) ? a1[i] : a2[i - 384];

    // A = split(x): 96 rows x 192
    for (int idx = tid; idx < MR * 96; idx += THREADS) {
        int r = idx / 96, kp = idx % 96;
        float2 v = make_float2(0.f, 0.f);
        if (r < nrows) v = *(const float2*)(x + (row0 + r) * Fd + kp * 2);
        u16 h0,l0,h1,l1;
        split_bf16(v.x, h0, l0); split_bf16(v.y, h1, l1);
        *(u32*)(smc + OFF_AHI + r * ASTR + kp * 4) = h0 | ((u32)h1 << 16);
        *(u32*)(smc + OFF_ALO + r * ASTR + kp * 4) = l0 | ((u32)l1 << 16);
    }

    for (int h = 0; h < 2; h++) {
        float acc[3][3][4];
#pragma unroll
        for (int mt = 0; mt < 3; mt++)
#pragma unroll
            for (int nt = 0; nt < 3; nt++)
#pragma unroll
                for (int p = 0; p < 4; p++) acc[mt][nt][p] = 0.0f;

        gemm6(sb, acc, g_w12t_hi + h * 192 * 192, g_w12t_lo + h * 192 * 192, 192,
              tid, wm, wn, lane);

        __syncthreads();
#pragma unroll
        for (int mt = 0; mt < 3; mt++)
#pragma unroll
            for (int nt = 0; nt < 3; nt++) {
                int r = wm * 48 + mt * 16 + l4, c = wn * 24 + nt * 8 + lq * 2;
                whs[r * WS_S + c]           = acc[mt][nt][0];
                whs[r * WS_S + c + 1]       = acc[mt][nt][1];
                whs[(r + 8) * WS_S + c]     = acc[mt][nt][2];
                whs[(r + 8) * WS_S + c + 1] = acc[mt][nt][3];
            }
        __syncthreads();

        // attention head h: warp (wb, q): q -> (sd, ihalf)
        float* ev   = smf + OFF_WS / 4 + wb * 550;
        float* attw = ev + 44;
        if (wb < nb) {
            const int sd = q >> 1, i0 = (q & 1) * 11;
            const float* av = avs + h * 384 + sd * 192;
            for (int i = i0; i < i0 + 11; i++) {
                const float* rw = whs + (wb * Nn + i) * WS_S;
                float s = 0.0f;
#pragma unroll
                for (int j = 0; j < 6; j++) s += rw[lane + 32 * j] * av[lane + 32 * j];
#pragma unroll
                for (int o = 16; o; o >>= 1) s += __shfl_xor_sync(0xffffffffu, s, o);
                if (lane == 0) ev[sd * Nn + i] = s;
            }
        }
        __syncthreads();
        if (wb < nb && q == 0) warp_softmax(ev, adjs, attw, lane);
        __syncthreads();
        if (wb < nb) {
            // warp (wb, q): 48 cols [q*48, q*48+48)
#pragma unroll
            for (int p = 0; p < 2; p++) {
                int c = q * 48 + p * 32 + lane;
                bool act = (p == 0) || (lane < 16);
                if (act) {
                    float wv[Nn];
#pragma unroll
                    for (int j = 0; j < Nn; j++) wv[j] = whs[(wb * Nn + j) * WS_S + c];
#pragma unroll 2
                    for (int i = 0; i < Nn; i++) {
                        const float* aw = attw + i * 23;
                        float s = 0.0f;
#pragma unroll
                        for (int j = 0; j < Nn; j++) s += aw[j] * wv[j];
                        s = elu1(s);
                        u16 hh, ll; split_bf16(s, hh, ll);
                        g_hcp[(row0 + wb * Nn + i) * 384 + h * 192 + c] = ((u32)hh << 16) | ll;
                    }
                }
            }
        }
        __syncthreads();
    }
}

// ================= K2: GEMM2 (K=384) + output attention + residual =================
__global__ __launch_bounds__(THREADS, 1)
void k2(const float* __restrict__ x, const float* __restrict__ adj,
        const float* __restrict__ ao, float* __restrict__ out, int nbatch)
{
    extern __shared__ char smc[];
    float* smf = (float*)smc;
    const u32 sb = smem_u32(smc);
    const int tid = threadIdx.x, wid = tid >> 5, lane = tid & 31;
    const int l4 = lane >> 2, lq = lane & 3;
    const int wm = wid & 1, wn = wid >> 1;
    const int wb = wid >> 2, q = wid & 3;
    const int b0 = blockIdx.x * NB4;
    const int nb = min(NB4, nbatch - b0);
    const int nrows = nb * Nn;
    const long long row0 = (long long)b0 * Nn;

    float* adjs = smf + OFF_ADJ / 4;
    float* avs  = smf + OFF_AVS / 4;
    float* who  = (float*)(smc + OFF_WHS);

    for (int i = tid; i < Nn * Nn; i += THREADS) adjs[i] = adj[i];
    for (int i = tid; i < 384; i += THREADS) avs[i] = ao[i];

    float acc[3][3][4];
#pragma unroll
    for (int mt = 0; mt < 3; mt++)
#pragma unroll
        for (int nt = 0; nt < 3; nt++)
#pragma unroll
            for (int p = 0; p < 4; p++) acc[mt][nt][p] = 0.0f;

    for (int kh = 0; kh < 2; kh++) {
        __syncthreads();   // prior A reads complete before overwrite
        // load packed A half from g_hcp, unpack to hi/lo planes
        for (int idx = tid; idx < MR * 48; idx += THREADS) {
            int r = idx / 48, q4 = (idx % 48) * 4;
            uint4 v = make_uint4(0, 0, 0, 0);
            if (r < nrows)
                v = *(const uint4*)(g_hcp + (row0 + r) * 384 + kh * 192 + q4);
            u32 hi0 = __byte_perm(v.x, v.y, 0x7632);
            u32 lo0 = __byte_perm(v.x, v.y, 0x5410);
            u32 hi1 = __byte_perm(v.z, v.w, 0x7632);
            u32 lo1 = __byte_perm(v.z, v.w, 0x5410);
            *(uint2*)(smc + OFF_AHI + r * ASTR + q4 * 2) = make_uint2(hi0, hi1);
            *(uint2*)(smc + OFF_ALO + r * ASTR + q4 * 2) = make_uint2(lo0, lo1);
        }
        gemm6(sb, acc, g_wot_hi + kh * 192, g_wot_lo + kh * 192, 384,
              tid, wm, wn, lane);
    }

    __syncthreads();
#pragma unroll
    for (int mt = 0; mt < 3; mt++)
#pragma unroll
        for (int nt = 0; nt < 3; nt++) {
            int r = wm * 48 + mt * 16 + l4, c = wn * 24 + nt * 8 + lq * 2;
            who[r * WS_S + c]           = acc[mt][nt][0];
            who[r * WS_S + c + 1]       = acc[mt][nt][1];
            who[(r + 8) * WS_S + c]     = acc[mt][nt][2];
            who[(r + 8) * WS_S + c + 1] = acc[mt][nt][3];
        }
    __syncthreads();

    float* ev   = smf + OFF_WS / 4 + wb * 550;
    float* attw = ev + 44;
    if (wb < nb) {
        const int sd = q >> 1, i0 = (q & 1) * 11;
        const float* av = avs + sd * 192;
        for (int i = i0; i < i0 + 11; i++) {
            const float* rw = who + (wb * Nn + i) * WS_S;
            float s = 0.0f;
#pragma unroll
            for (int j = 0; j < 6; j++) s += rw[lane + 32 * j] * av[lane + 32 * j];
#pragma unroll
            for (int o = 16; o; o >>= 1) s += __shfl_xor_sync(0xffffffffu, s, o);
            if (lane == 0) ev[sd * Nn + i] = s;
        }
    }
    __syncthreads();
    if (wb < nb && q == 0) warp_softmax(ev, adjs, attw, lane);
    __syncthreads();
    if (wb < nb) {
#pragma unroll
        for (int p = 0; p < 2; p++) {
            int c = q * 48 + p * 32 + lane;
            bool act = (p == 0) || (lane < 16);
            if (act) {
                float wv[Nn];
#pragma unroll
                for (int j = 0; j < Nn; j++) wv[j] = who[(wb * Nn + j) * WS_S + c];
#pragma unroll 2
                for (int i = 0; i < Nn; i++) {
                    const float* aw = attw + i * 23;
                    float s = 0.0f;
#pragma unroll
                    for (int j = 0; j < Nn; j++) s += aw[j] * wv[j];
                    long long gi = (row0 + wb * Nn + i) * Fd + c;
                    out[gi] = elu1(s) + x[gi];
                }
            }
        }
    }
}

extern "C" void kernel_launch(void* const* d_in, const int* in_sizes, int n_in,
                              void* d_out, int out_size)
{
    const float* x   = (const float*)d_in[0];
    const float* adj = (const float*)d_in[1];
    const float* W1  = (const float*)d_in[2];
    const float* a1  = (const float*)d_in[3];
    const float* W2  = (const float*)d_in[4];
    const float* a2  = (const float*)d_in[5];
    const float* Wo  = (const float*)d_in[6];
    const float* ao  = (const float*)d_in[7];
    float* out = (float*)d_out;

    int nbatch = in_sizes[0] / (Nn * Fd);
    int ctas = (nbatch + NB4 - 1) / NB4;

    cudaFuncSetAttribute(k1, cudaFuncAttributeMaxDynamicSharedMemorySize, SMEM_TOTAL);
    cudaFuncSetAttribute(k2, cudaFuncAttributeMaxDynamicSharedMemorySize, SMEM_TOTAL);

    k_prep<<<(2 * 384 * 192 + 255) / 256, 256>>>(W1, W2, Wo);
    k1<<<ctas, THREADS, SMEM_TOTAL>>>(x, adj, a1, a2, nbatch);
    k2<<<ctas, THREADS, SMEM_TOTAL>>>(x, adj, ao, out, nbatch);
}

// round 8
// speedup vs baseline: 1.2942x; 1.0600x over previous
#include <cuda_runtime.h>
#include <cuda_bf16.h>

#define Nn 22
#define Fd 192
#define NB4 4
#define MR 96
#define THREADS 512

typedef unsigned int u32;
typedef unsigned short u16;

// ---- SMEM layout (bytes) ----
#define OFF_ADJ 0            // 484 f
#define OFF_AVS 1952         // 1152 f (a1,a2,ao)
#define OFF_WS  6560         // 4 x 550 f
#define OFF_A   15360
#define ASTR    400          // 96 rows x 192 bf16 (16B-aligned, LDSM conflict-free)
#define OFF_AHI OFF_A
#define OFF_ALO (OFF_A + 38400)
#define OFF_B   92160        // dbuf: per buf hi plane 15360 + lo plane 15360
#define BSTR    80           // 192 rows x 32 bf16
#define BPL     15360
#define BBUF    30720
#define OFF_WHS 153600       // 96 x 193 fp32 (Wh per head; later who)
#define WS_S    193
#define SMEM_TOTAL 227712

// ---- device-global weight splits (sanctioned scratch) ----
static __device__ __nv_bfloat16 g_w12t_hi[384*192];
static __device__ __nv_bfloat16 g_w12t_lo[384*192];
static __device__ __nv_bfloat16 g_wot_hi[192*384];
static __device__ __nv_bfloat16 g_wot_lo[192*384];

// ---- helpers ----
__device__ __forceinline__ u32 smem_u32(const void* p){
    u32 a;
    asm("{ .reg .u64 t; cvta.to.shared.u64 t, %1; cvt.u32.u64 %0, t; }" : "=r"(a) : "l"(p));
    return a;
}
__device__ __forceinline__ void split_bf16(float v, u16& h, u16& l){
    __nv_bfloat16 hb = __float2bfloat16(v);
    float hf = __bfloat162float(hb);
    __nv_bfloat16 lb = __float2bfloat16(v - hf);
    h = __bfloat16_as_ushort(hb);
    l = __bfloat16_as_ushort(lb);
}
__device__ __forceinline__ float elu1(float v){ return (v > 0.0f) ? v : (__expf(v) - 1.0f); }

#define CPA16(sa, g) asm volatile("cp.async.cg.shared.global [%0], [%1], 16;" :: "r"((u32)(sa)), "l"(g) : "memory")
#define CPC()  asm volatile("cp.async.commit_group;" ::: "memory")
#define CPW1() asm volatile("cp.async.wait_group 1;" ::: "memory")
#define CPW0() asm volatile("cp.async.wait_group 0;" ::: "memory")

__device__ __forceinline__ void mma_bf16(float* c, const u32* a, u32 b0, u32 b1){
    asm volatile("mma.sync.aligned.m16n8k16.row.col.f32.bf16.bf16.f32 "
        "{%0,%1,%2,%3}, {%4,%5,%6,%7}, {%8,%9}, {%0,%1,%2,%3};"
        : "+f"(c[0]),"+f"(c[1]),"+f"(c[2]),"+f"(c[3])
        : "r"(a[0]),"r"(a[1]),"r"(a[2]),"r"(a[3]),"r"(b0),"r"(b1));
}
__device__ __forceinline__ void ldsm4(u32 a, u32* r){
    asm volatile("ldmatrix.sync.aligned.m8n8.x4.shared.b16 {%0,%1,%2,%3}, [%4];"
        : "=r"(r[0]),"=r"(r[1]),"=r"(r[2]),"=r"(r[3]) : "r"(a));
}
__device__ __forceinline__ void ldsm2(u32 a, u32* r){
    asm volatile("ldmatrix.sync.aligned.m8n8.x2.shared.b16 {%0,%1}, [%2];"
        : "=r"(r[0]),"=r"(r[1]) : "r"(a));
}

__device__ __forceinline__ void warp_softmax(const float* __restrict__ ev, const float* __restrict__ adjs,
                                             float* __restrict__ attw, int lane)
{
    if (lane < Nn) {
        int i = lane;
        float esrc = ev[i];
        float vals[Nn];
        float mx = -1e30f;
#pragma unroll
        for (int j = 0; j < Nn; j++) {
            if (adjs[i * Nn + j] != 0.0f) {
                float v = esrc + ev[Nn + j];
                v = (v > 0.0f) ? v : 0.2f * v;
                vals[j] = v;
                mx = fmaxf(mx, v);
            } else vals[j] = -1e30f;
        }
        float ssum = 0.0f;
#pragma unroll
        for (int j = 0; j < Nn; j++) {
            float e = (vals[j] > -1e29f) ? __expf(vals[j] - mx) : 0.0f;
            vals[j] = e; ssum += e;
        }
        float inv = 1.0f / ssum;
#pragma unroll
        for (int j = 0; j < Nn; j++) attw[i * 23 + j] = vals[j] * inv;
    }
}

// stream one B chunk: 192 n-rows x 32 k (hi+lo) via cp.async 16B
__device__ __forceinline__ void issue_b(u32 dst, const __nv_bfloat16* gh, const __nv_bfloat16* gl,
                                        int tid, int rs)
{
#pragma unroll
    for (int q = 0; q < 3; q++) {
        int lin = tid + THREADS * q;        // 0..1535
        int plane = lin / 768;
        int rem = lin - plane * 768;
        int row = rem >> 2, piece = rem & 3;
        const __nv_bfloat16* src = (plane ? gl : gh) + row * rs + piece * 8;
        CPA16(dst + plane * BPL + row * BSTR + piece * 16, src);
    }
}

// GEMM mainloop over 6 k-chunks against resident A; warp tile 48x24; acc[3][3][4]
__device__ __forceinline__ void gemm6(u32 sb, float acc[3][3][4],
                                      const __nv_bfloat16* bh0, const __nv_bfloat16* bl0, int rs,
                                      int tid, int wm, int wn, int lane)
{
    const u32 laneA = (u32)((lane & 15) * ASTR + (lane >> 4) * 16);
    const u32 laneB = (u32)((lane & 7) * BSTR + ((lane >> 3) & 1) * 16);
    const u32 Abase = sb + OFF_AHI + wm * 48 * ASTR + laneA;
    const u32 Bbase = sb + OFF_B + wn * 24 * BSTR + laneB;

    issue_b(sb + OFF_B, bh0, bl0, tid, rs);
    CPC();
    for (int kc = 0; kc < 6; kc++) {
        int buf = kc & 1;
        __syncthreads();
        if (kc < 5) {
            issue_b(sb + OFF_B + (buf ^ 1) * BBUF, bh0 + (kc + 1) * 32, bl0 + (kc + 1) * 32, tid, rs);
            CPC(); CPW1();
        } else CPW0();
        __syncthreads();

        const u32 Ah = Abase + kc * 64;
        const u32 Bh = Bbase + buf * BBUF;
#pragma unroll
        for (int s = 0; s < 2; s++) {
            u32 ah[3][4], al[3][4], bh[3][2], bl[3][2];
#pragma unroll
            for (int mt = 0; mt < 3; mt++) {
                ldsm4(Ah + mt * 16 * ASTR + s * 32, ah[mt]);
                ldsm4(Ah + 38400 + mt * 16 * ASTR + s * 32, al[mt]);
            }
#pragma unroll
            for (int t = 0; t < 3; t++) {
                ldsm2(Bh + t * 8 * BSTR + s * 32, bh[t]);
                ldsm2(Bh + BPL + t * 8 * BSTR + s * 32, bl[t]);
            }
#pragma unroll
            for (int mt = 0; mt < 3; mt++)
#pragma unroll
                for (int t = 0; t < 3; t++) {
                    mma_bf16(acc[mt][t], ah[mt], bh[t][0], bh[t][1]);
                    mma_bf16(acc[mt][t], ah[mt], bl[t][0], bl[t][1]);
                    mma_bf16(acc[mt][t], al[mt], bh[t][0], bh[t][1]);
                }
        }
    }
}

// ================= prep =================
__global__ void k_prep(const float* __restrict__ W1, const float* __restrict__ W2,
                       const float* __restrict__ Wo)
{
    int idx = blockIdx.x * blockDim.x + threadIdx.x;
    if (idx < 384 * 192) {
        int n = idx / 192, k = idx % 192;
        float v = (n < 192) ? W1[k * 192 + n] : W2[k * 192 + (n - 192)];
        u16 h, l; split_bf16(v, h, l);
        g_w12t_hi[idx] = __ushort_as_bfloat16(h);
        g_w12t_lo[idx] = __ushort_as_bfloat16(l);
    } else if (idx < 2 * 384 * 192) {
        int j = idx - 384 * 192;
        int n = j / 384, k = j % 384;
        float v = Wo[k * 192 + n];
        u16 h, l; split_bf16(v, h, l);
        g_wot_hi[j] = __ushort_as_bfloat16(h);
        g_wot_lo[j] = __ushort_as_bfloat16(l);
    }
}

// ================= fused: GEMM1+att per head interleaved with GEMM2 halves =================
__global__ __launch_bounds__(THREADS, 1)
void k_fused(const float* __restrict__ x, const float* __restrict__ adj,
             const float* __restrict__ a1, const float* __restrict__ a2,
             const float* __restrict__ ao, float* __restrict__ out, int nbatch)
{
    extern __shared__ char smc[];
    float* smf = (float*)smc;
    const u32 sb = smem_u32(smc);
    const int tid = threadIdx.x, wid = tid >> 5, lane = tid & 31;
    const int l4 = lane >> 2, lq = lane & 3;
    const int wm = wid & 1, wn = wid >> 1;       // GEMM roles: 2M x 8N
    const int wb = wid >> 2, q = wid & 3;        // attention roles: 4 batches x 4 slices
    const int b0 = blockIdx.x * NB4;
    const int nb = min(NB4, nbatch - b0);
    const int nrows = nb * Nn;
    const long long row0 = (long long)b0 * Nn;

    float* adjs = smf + OFF_ADJ / 4;
    float* avs  = smf + OFF_AVS / 4;
    float* whs  = (float*)(smc + OFF_WHS);       // Wh per head; later who

    for (int i = tid; i < Nn * Nn; i += THREADS) adjs[i] = adj[i];
    for (int i = tid; i < 1152; i += THREADS)
        avs[i] = (i < 384) ? a1[i] : (i < 768 ? a2[i - 384] : ao[i - 768]);

    // GEMM2 accumulators persist across both k-halves
    float acc2[3][3][4];
#pragma unroll
    for (int mt = 0; mt < 3; mt++)
#pragma unroll
        for (int nt = 0; nt < 3; nt++)
#pragma unroll
            for (int p = 0; p < 4; p++) acc2[mt][nt][p] = 0.0f;

    for (int h = 0; h < 2; h++) {
        // ---- load + split x into A planes (pad rows zeroed) ----
        __syncthreads();   // prior A reads (GEMM2 p0) complete before overwrite
        for (int idx = tid; idx < MR * 96; idx += THREADS) {
            int r = idx / 96, kp = idx % 96;
            float2 v = make_float2(0.f, 0.f);
            if (r < nrows) v = *(const float2*)(x + (row0 + r) * Fd + kp * 2);
            u16 h0,l0,h1,l1;
            split_bf16(v.x, h0, l0); split_bf16(v.y, h1, l1);
            *(u32*)(smc + OFF_AHI + r * ASTR + kp * 4) = h0 | ((u32)h1 << 16);
            *(u32*)(smc + OFF_ALO + r * ASTR + kp * 4) = l0 | ((u32)l1 << 16);
        }

        // ---- GEMM1 head h: Wh = x @ Wh_h ----
        {
            float acc[3][3][4];
#pragma unroll
            for (int mt = 0; mt < 3; mt++)
#pragma unroll
                for (int nt = 0; nt < 3; nt++)
#pragma unroll
                    for (int p = 0; p < 4; p++) acc[mt][nt][p] = 0.0f;

            gemm6(sb, acc, g_w12t_hi + h * 192 * 192, g_w12t_lo + h * 192 * 192, 192,
                  tid, wm, wn, lane);

            __syncthreads();
#pragma unroll
            for (int mt = 0; mt < 3; mt++)
#pragma unroll
                for (int nt = 0; nt < 3; nt++) {
                    int r = wm * 48 + mt * 16 + l4, c = wn * 24 + nt * 8 + lq * 2;
                    whs[r * WS_S + c]           = acc[mt][nt][0];
                    whs[r * WS_S + c + 1]       = acc[mt][nt][1];
                    whs[(r + 8) * WS_S + c]     = acc[mt][nt][2];
                    whs[(r + 8) * WS_S + c + 1] = acc[mt][nt][3];
                }
        }
        __syncthreads();

        // ---- attention head h; hc written split into A planes ----
        float* ev   = smf + OFF_WS / 4 + wb * 550;
        float* attw = ev + 44;
        {
            const int sd = q >> 1, i0 = (q & 1) * 11;
            const float* av = avs + h * 384 + sd * 192;
            for (int i = i0; i < i0 + 11; i++) {
                const float* rw = whs + (wb * Nn + i) * WS_S;
                float s = 0.0f;
#pragma unroll
                for (int j = 0; j < 6; j++) s += rw[lane + 32 * j] * av[lane + 32 * j];
#pragma unroll
                for (int o = 16; o; o >>= 1) s += __shfl_xor_sync(0xffffffffu, s, o);
                if (lane == 0) ev[sd * Nn + i] = s;
            }
        }
        __syncthreads();
        if (q == 0) warp_softmax(ev, adjs, attw, lane);
        __syncthreads();
#pragma unroll
        for (int p = 0; p < 2; p++) {
            int c = q * 48 + p * 32 + lane;
            bool act = (p == 0) || (lane < 16);
            if (act) {
                float wv[Nn];
#pragma unroll
                for (int j = 0; j < Nn; j++) wv[j] = whs[(wb * Nn + j) * WS_S + c];
#pragma unroll 2
                for (int i = 0; i < Nn; i++) {
                    const float* aw = attw + i * 23;
                    float s = 0.0f;
#pragma unroll
                    for (int j = 0; j < Nn; j++) s += aw[j] * wv[j];
                    s = elu1(s);
                    u16 hh, ll; split_bf16(s, hh, ll);
                    int rr = wb * Nn + i;
                    *(u16*)(smc + OFF_AHI + rr * ASTR + c * 2) = hh;
                    *(u16*)(smc + OFF_ALO + rr * ASTR + c * 2) = ll;
                }
            }
        }
        // gemm6's internal syncs order these writes before its A reads

        // ---- GEMM2 partial: k-half h, A = hc_h (in A planes), B = Wot k-cols ----
        gemm6(sb, acc2, g_wot_hi + h * 192, g_wot_lo + h * 192, 384,
              tid, wm, wn, lane);
    }

    // ---- epilogue: acc2 -> who (whs region) ----
    __syncthreads();
#pragma unroll
    for (int mt = 0; mt < 3; mt++)
#pragma unroll
        for (int nt = 0; nt < 3; nt++) {
            int r = wm * 48 + mt * 16 + l4, c = wn * 24 + nt * 8 + lq * 2;
            whs[r * WS_S + c]           = acc2[mt][nt][0];
            whs[r * WS_S + c + 1]       = acc2[mt][nt][1];
            whs[(r + 8) * WS_S + c]     = acc2[mt][nt][2];
            whs[(r + 8) * WS_S + c + 1] = acc2[mt][nt][3];
        }
    __syncthreads();

    // ---- output attention + elu + residual ----
    float* ev   = smf + OFF_WS / 4 + wb * 550;
    float* attw = ev + 44;
    {
        const int sd = q >> 1, i0 = (q & 1) * 11;
        const float* av = avs + 768 + sd * 192;
        for (int i = i0; i < i0 + 11; i++) {
            const float* rw = whs + (wb * Nn + i) * WS_S;
            float s = 0.0f;
#pragma unroll
            for (int j = 0; j < 6; j++) s += rw[lane + 32 * j] * av[lane + 32 * j];
#pragma unroll
            for (int o = 16; o; o >>= 1) s += __shfl_xor_sync(0xffffffffu, s, o);
            if (lane == 0) ev[sd * Nn + i] = s;
        }
    }
    __syncthreads();
    if (q == 0) warp_softmax(ev, adjs, attw, lane);
    __syncthreads();
#pragma unroll
    for (int p = 0; p < 2; p++) {
        int c = q * 48 + p * 32 + lane;
        bool act = (p == 0) || (lane < 16);
        if (act) {
            float wv[Nn];
#pragma unroll
            for (int j = 0; j < Nn; j++) wv[j] = whs[(wb * Nn + j) * WS_S + c];
#pragma unroll 2
            for (int i = 0; i < Nn; i++) {
                const float* aw = attw + i * 23;
                float s = 0.0f;
#pragma unroll
                for (int j = 0; j < Nn; j++) s += aw[j] * wv[j];
                long long gi = (row0 + wb * Nn + i) * Fd + c;
                out[gi] = elu1(s) + x[gi];
            }
        }
    }
}

extern "C" void kernel_launch(void* const* d_in, const int* in_sizes, int n_in,
                              void* d_out, int out_size)
{
    const float* x   = (const float*)d_in[0];
    const float* adj = (const float*)d_in[1];
    const float* W1  = (const float*)d_in[2];
    const float* a1  = (const float*)d_in[3];
    const float* W2  = (const float*)d_in[4];
    const float* a2  = (const float*)d_in[5];
    const float* Wo  = (const float*)d_in[6];
    const float* ao  = (const float*)d_in[7];
    float* out = (float*)d_out;

    int nbatch = in_sizes[0] / (Nn * Fd);
    int ctas = (nbatch + NB4 - 1) / NB4;

    cudaFuncSetAttribute(k_fused, cudaFuncAttributeMaxDynamicSharedMemorySize, SMEM_TOTAL);

    k_prep<<<(2 * 384 * 192 + 255) / 256, 256>>>(W1, W2, Wo);
    k_fused<<<ctas, THREADS, SMEM_TOTAL>>>(x, adj, a1, a2, ao, out, nbatch);
}